// round 1
// baseline (speedup 1.0000x reference)
#include <cuda_runtime.h>
#include <float.h>

#define NB 4
#define CC 96
#define NN 3136
#define KNN 9
#define CMM 192
#define HH 56

// ---------------- scratch (device globals: allocation-free) ----------------
__device__ float g_h[NB * CC * NN];                    // fc1 output [b][c][n]
__device__ float g_x2[NB * NN];                        // sum h^2 per node
__device__ float g_D[(size_t)NB * NN * NN];            // reduced dist x2[m]-2*inner (157MB)
__device__ int   g_idx[NB * NN * KNN];                 // knn indices
__device__ float g_uv[(size_t)NB * NN * (2 * CMM)];    // [b][n][0..191]=u, [192..383]=v
__device__ float g_out[NB * CC * NN];                  // pre-attention out [b][o][n]
__device__ float g_avg[NB * NN];
__device__ float g_mx[NB * NN];

// ---------------- K1: fc1 (h = W x + b) and x2 ----------------
__global__ void k_fc1(const float* __restrict__ x, const float* __restrict__ w,
                      const float* __restrict__ bias) {
    __shared__ __align__(16) float Xs[96][64];
    __shared__ float Ws[32][96];
    __shared__ float S2[256];
    int b = blockIdx.y;
    int n0 = blockIdx.x * 64;
    int tid = threadIdx.x;

    for (int i = tid; i < 96 * 64; i += 256) {
        int c = i >> 6, j = i & 63;
        Xs[c][j] = x[((b * 96) + c) * NN + n0 + j];
    }
    int oz = tid >> 6;   // 0..3
    int j  = tid & 63;
    float s2 = 0.f;

    for (int oc = 0; oc < 3; oc++) {
        __syncthreads();
        for (int i = tid; i < 32 * 96; i += 256) {
            int oo = i / 96, c = i % 96;
            Ws[oo][c] = w[(oc * 32 + oo) * 96 + c];
        }
        __syncthreads();
        float acc[8];
#pragma unroll
        for (int q = 0; q < 8; q++) acc[q] = bias[oc * 32 + oz * 8 + q];
        for (int c = 0; c < 96; c++) {
            float xc = Xs[c][j];
#pragma unroll
            for (int q = 0; q < 8; q++) acc[q] += Ws[oz * 8 + q][c] * xc;
        }
#pragma unroll
        for (int q = 0; q < 8; q++) {
            int o = oc * 32 + oz * 8 + q;
            g_h[((b * 96) + o) * NN + n0 + j] = acc[q];
            s2 += acc[q] * acc[q];
        }
    }
    S2[tid] = s2;
    __syncthreads();
    if (oz == 0) {
        float t = S2[j] + S2[64 + j] + S2[128 + j] + S2[192 + j];
        g_x2[b * NN + n0 + j] = t;
    }
}

// ---------------- K2: reduced distance GEMM (symmetric, 64x64 tiles) ----------------
__global__ void k_dist() {
    int bi = blockIdx.x, bj = blockIdx.y, b = blockIdx.z;
    if (bi > bj) return;
    __shared__ __align__(16) float As[48][64];
    __shared__ __align__(16) float Bs[48][64];
    __shared__ float x2i[64], x2j[64];

    int tid = threadIdx.x;
    int tx = tid & 15, ty = tid >> 4;
    int ni0 = bi * 64, nj0 = bj * 64;
    if (tid < 64) x2i[tid] = g_x2[b * NN + ni0 + tid];
    else if (tid < 128) x2j[tid - 64] = g_x2[b * NN + nj0 + tid - 64];

    const float* hb = g_h + (size_t)b * 96 * NN;
    float acc[4][4] = {};

    for (int kc = 0; kc < 2; kc++) {
        __syncthreads();
        for (int i = tid; i < 48 * 64; i += 256) {
            int c = i >> 6, jj = i & 63;
            As[c][jj] = hb[(kc * 48 + c) * NN + ni0 + jj];
            Bs[c][jj] = hb[(kc * 48 + c) * NN + nj0 + jj];
        }
        __syncthreads();
#pragma unroll
        for (int k = 0; k < 48; k++) {
            float4 a = *(const float4*)&As[k][ty * 4];
            float4 bb = *(const float4*)&Bs[k][tx * 4];
            float ar[4] = {a.x, a.y, a.z, a.w};
            float br[4] = {bb.x, bb.y, bb.z, bb.w};
#pragma unroll
            for (int ii = 0; ii < 4; ii++)
#pragma unroll
                for (int jj = 0; jj < 4; jj++) acc[ii][jj] += ar[ii] * br[jj];
        }
    }
    float x2jv[4], x2iv[4];
#pragma unroll
    for (int t = 0; t < 4; t++) { x2jv[t] = x2j[tx * 4 + t]; x2iv[t] = x2i[ty * 4 + t]; }

#pragma unroll
    for (int ii = 0; ii < 4; ii++) {
        int ni = ni0 + ty * 4 + ii;
        float4 v;
        v.x = x2jv[0] - 2.f * acc[ii][0];
        v.y = x2jv[1] - 2.f * acc[ii][1];
        v.z = x2jv[2] - 2.f * acc[ii][2];
        v.w = x2jv[3] - 2.f * acc[ii][3];
        *(float4*)&g_D[((size_t)(b * NN + ni)) * NN + nj0 + tx * 4] = v;
    }
    if (bi < bj) {
#pragma unroll
        for (int jj = 0; jj < 4; jj++) {
            int nj = nj0 + tx * 4 + jj;
            float4 v;
            v.x = x2iv[0] - 2.f * acc[0][jj];
            v.y = x2iv[1] - 2.f * acc[1][jj];
            v.z = x2iv[2] - 2.f * acc[2][jj];
            v.w = x2iv[3] - 2.f * acc[3][jj];
            *(float4*)&g_D[((size_t)(b * NN + nj)) * NN + ni0 + ty * 4] = v;
        }
    }
}

// ---------------- K3: top-9 smallest per row (warp per row) ----------------
__device__ __forceinline__ bool knn_less(float d1, int i1, float d2, int i2) {
    return d1 < d2 || (d1 == d2 && i1 < i2);
}

__global__ void k_topk() {
    int warp = threadIdx.x >> 5;
    int lane = threadIdx.x & 31;
    int row = blockIdx.x * 8 + warp;        // row = b*NN + n, total 12544
    const float* Drow = g_D + (size_t)row * NN;

    float ad[9];
    int   ai[9];
#pragma unroll
    for (int p = 0; p < 9; p++) { ad[p] = FLT_MAX; ai[p] = 0x7fffffff; }

    for (int m = lane; m < NN; m += 32) {
        float d = Drow[m];
        if (knn_less(d, m, ad[8], ai[8])) {
            ad[8] = d; ai[8] = m;
#pragma unroll
            for (int p = 8; p > 0; p--) {
                if (knn_less(ad[p], ai[p], ad[p - 1], ai[p - 1])) {
                    float td = ad[p]; ad[p] = ad[p - 1]; ad[p - 1] = td;
                    int   ti = ai[p]; ai[p] = ai[p - 1]; ai[p - 1] = ti;
                }
            }
        }
    }
    // 9 rounds of warp-min merge
    for (int kk = 0; kk < 9; kk++) {
        float d = ad[0]; int ix = ai[0];
#pragma unroll
        for (int off = 16; off > 0; off >>= 1) {
            float od = __shfl_down_sync(0xffffffffu, d, off);
            int   oi = __shfl_down_sync(0xffffffffu, ix, off);
            if (knn_less(od, oi, d, ix)) { d = od; ix = oi; }
        }
        ix = __shfl_sync(0xffffffffu, ix, 0);
        if (ai[0] == ix) {  // winner lane pops (indices unique per lane)
#pragma unroll
            for (int p = 0; p < 8; p++) { ad[p] = ad[p + 1]; ai[p] = ai[p + 1]; }
            ad[8] = FLT_MAX; ai[8] = 0x7fffffff;
        }
        if (lane == 0) g_idx[row * 9 + kk] = ix;
    }
}

// ---------------- K4: u/v GEMM (384x96 @ 96xN), output node-major ----------------
__global__ void k_uv(const float* __restrict__ gw, const float* __restrict__ gb) {
    int bn = blockIdx.x;       // 0..48  (n tile)
    int br = blockIdx.y;       // 0..5   (row tile of 384)
    int b  = blockIdx.z;
    __shared__ __align__(16) float As2[64][48];   // [row_local][k]
    __shared__ __align__(16) float Bs[48][64];    // [k][n_local]
    int tid = threadIdx.x, tx = tid & 15, ty = tid >> 4;
    int r0 = br * 64, n0 = bn * 64;
    bool is_u = (r0 < 192);
    const float* hb = g_h + (size_t)b * 96 * NN;
    float acc[4][4] = {};

    for (int kc = 0; kc < 2; kc++) {
        __syncthreads();
        for (int i = tid; i < 64 * 48; i += 256) {
            int rl = i / 48, cl = i % 48;
            int c = kc * 48 + cl;
            int r = r0 + rl;
            float wv;
            if (is_u) wv = gw[r * 192 + c] - gw[r * 192 + 96 + c];
            else      wv = gw[(r - 192) * 192 + 96 + c];
            As2[rl][cl] = wv;
        }
        for (int i = tid; i < 48 * 64; i += 256) {
            int c = i >> 6, jj = i & 63;
            Bs[c][jj] = hb[(kc * 48 + c) * NN + n0 + jj];
        }
        __syncthreads();
#pragma unroll
        for (int k4 = 0; k4 < 48; k4 += 4) {
            float4 a0 = *(const float4*)&As2[ty * 4 + 0][k4];
            float4 a1 = *(const float4*)&As2[ty * 4 + 1][k4];
            float4 a2 = *(const float4*)&As2[ty * 4 + 2][k4];
            float4 a3 = *(const float4*)&As2[ty * 4 + 3][k4];
            float4 b0 = *(const float4*)&Bs[k4 + 0][tx * 4];
            float4 b1 = *(const float4*)&Bs[k4 + 1][tx * 4];
            float4 b2 = *(const float4*)&Bs[k4 + 2][tx * 4];
            float4 b3 = *(const float4*)&Bs[k4 + 3][tx * 4];
            float ar[4][4] = {{a0.x,a0.y,a0.z,a0.w},{a1.x,a1.y,a1.z,a1.w},
                              {a2.x,a2.y,a2.z,a2.w},{a3.x,a3.y,a3.z,a3.w}};
            float br2[4][4] = {{b0.x,b0.y,b0.z,b0.w},{b1.x,b1.y,b1.z,b1.w},
                               {b2.x,b2.y,b2.z,b2.w},{b3.x,b3.y,b3.z,b3.w}};
#pragma unroll
            for (int ii = 0; ii < 4; ii++)
#pragma unroll
                for (int jj = 0; jj < 4; jj++) {
#pragma unroll
                    for (int kk = 0; kk < 4; kk++)
                        acc[ii][jj] += ar[ii][kk] * br2[kk][jj];
                }
        }
    }
    float bv[4] = {0.f, 0.f, 0.f, 0.f};
    if (is_u) {
#pragma unroll
        for (int ii = 0; ii < 4; ii++) bv[ii] = gb[r0 + ty * 4 + ii];
    }
#pragma unroll
    for (int jj = 0; jj < 4; jj++) {
        int n = n0 + tx * 4 + jj;
        float4 v;
        v.x = acc[0][jj] + bv[0];
        v.y = acc[1][jj] + bv[1];
        v.z = acc[2][jj] + bv[2];
        v.w = acc[3][jj] + bv[3];
        *(float4*)&g_uv[((size_t)b * NN + n) * 384 + r0 + ty * 4] = v;
    }
}

// ---------------- K5: gather+maxpool+relu + fc2 + channel avg/max ----------------
__global__ void k_gfc2(const float* __restrict__ fw, const float* __restrict__ fb) {
    __shared__ float Wf[32][193];
    __shared__ float gs[8][192];
    int tid = threadIdx.x;
    int warp = tid >> 5, lane = tid & 31;
    int node = blockIdx.x * 8 + warp;       // b*NN + n
    int b = node / NN, n = node % NN;
    const float* uvb = g_uv + (size_t)b * NN * 384;

    int nb[9];
#pragma unroll
    for (int k = 0; k < 9; k++) nb[k] = g_idx[node * 9 + k];

#pragma unroll
    for (int s = 0; s < 6; s++) {
        int c = lane + 32 * s;
        float u = uvb[(size_t)n * 384 + c];
        float m = -FLT_MAX;
#pragma unroll
        for (int k = 0; k < 9; k++)
            m = fmaxf(m, uvb[(size_t)nb[k] * 384 + 192 + c]);
        gs[warp][c] = fmaxf(u + m, 0.f);
    }
    __syncwarp();

    float ssum = 0.f, smax = -FLT_MAX;
    for (int ch = 0; ch < 3; ch++) {
        __syncthreads();
        for (int i = tid; i < 32 * 192; i += 256) {
            int oo = i / 192, c = i % 192;
            Wf[oo][c] = fw[(ch * 32 + oo) * 192 + c];
        }
        __syncthreads();
        int o = ch * 32 + lane;
        float a = fb[o];
        for (int c = 0; c < 192; c++) a += Wf[lane][c] * gs[warp][c];
        g_out[((b * 96) + o) * NN + n] = a;
        ssum += a;
        smax = fmaxf(smax, a);
    }
#pragma unroll
    for (int off = 16; off > 0; off >>= 1) {
        ssum += __shfl_down_sync(0xffffffffu, ssum, off);
        smax = fmaxf(smax, __shfl_down_sync(0xffffffffu, smax, off));
    }
    if (lane == 0) {
        g_avg[b * NN + n] = ssum * (1.f / 96.f);
        g_mx[b * NN + n] = smax;
    }
}

// ---------------- K6: 7x7 spatial attention + sigmoid + residual ----------------
__global__ void k_att(const float* __restrict__ sw_g, const float* __restrict__ x,
                      float* __restrict__ out) {
    __shared__ float sw[98];
    int tid = threadIdx.x;
    if (tid < 98) sw[tid] = sw_g[tid];
    __syncthreads();
    int b = blockIdx.y;
    int n = blockIdx.x * 256 + tid;
    if (n >= NN) return;
    int y = n / HH, x0 = n % HH;
    const float* avgb = g_avg + b * NN;
    const float* mxb  = g_mx + b * NN;
    float acc = 0.f;
#pragma unroll
    for (int dy = 0; dy < 7; dy++) {
        int yy = y + dy - 3;
        if ((unsigned)yy < HH) {
#pragma unroll
            for (int dx = 0; dx < 7; dx++) {
                int xx = x0 + dx - 3;
                if ((unsigned)xx < HH) {
                    int nn = yy * HH + xx;
                    acc += sw[dy * 7 + dx] * avgb[nn] + sw[49 + dy * 7 + dx] * mxb[nn];
                }
            }
        }
    }
    float att = 1.f / (1.f + expf(-acc));
    for (int o = 0; o < 96; o++) {
        size_t off = ((size_t)(b * 96 + o)) * NN + n;
        out[off] = g_out[off] * att + x[off];
    }
}

// ---------------- launch ----------------
extern "C" void kernel_launch(void* const* d_in, const int* in_sizes, int n_in,
                              void* d_out, int out_size) {
    const float* x       = (const float*)d_in[0];
    const float* fc1_w   = (const float*)d_in[1];
    const float* fc1_b   = (const float*)d_in[2];
    const float* gconv_w = (const float*)d_in[3];
    const float* gconv_b = (const float*)d_in[4];
    const float* fc2_w   = (const float*)d_in[5];
    const float* fc2_b   = (const float*)d_in[6];
    const float* sa_w    = (const float*)d_in[7];
    float* out = (float*)d_out;

    k_fc1 <<<dim3(49, 4), 256>>>(x, fc1_w, fc1_b);
    k_dist<<<dim3(49, 49, 4), 256>>>();
    k_topk<<<1568, 256>>>();
    k_uv  <<<dim3(49, 6, 4), 256>>>(gconv_w, gconv_b);
    k_gfc2<<<1568, 256>>>(fc2_w, fc2_b);
    k_att <<<dim3(13, 4), 256>>>(sa_w, x, out);
}

// round 2
// speedup vs baseline: 1.2528x; 1.2528x over previous
#include <cuda_runtime.h>
#include <float.h>
#include <math.h>

#define NB 4
#define CC 96
#define NN 3136
#define KNN 9
#define CMM 192
#define HH 56

// ---------------- scratch (device globals: allocation-free) ----------------
__device__ __align__(16) float g_h[NB * CC * NN];                 // fc1 output [b][c][n]
__device__ __align__(16) float g_x2[NB * NN];                     // sum h^2 per node
__device__ __align__(16) float g_D[(size_t)NB * NN * NN];         // reduced dist x2[j]-2*inner
__device__ __align__(16) int   g_idx[NB * NN * KNN];              // knn indices
__device__ __align__(16) float g_uv[(size_t)NB * NN * (2 * CMM)]; // [b][n][0..191]=u,[192..383]=v
__device__ __align__(16) float g_out[NB * CC * NN];               // pre-attention out [b][o][n]
__device__ __align__(16) float g_avg[NB * NN];
__device__ __align__(16) float g_mx[NB * NN];

// ---------------- K1: fc1 (h = W x + b) and x2 ----------------
__global__ void k_fc1(const float* __restrict__ x, const float* __restrict__ w,
                      const float* __restrict__ bias) {
    __shared__ __align__(16) float Xs[96][64];
    __shared__ float Ws[32][96];
    __shared__ float S2[256];
    int b = blockIdx.y;
    int n0 = blockIdx.x * 64;
    int tid = threadIdx.x;

    for (int i = tid; i < 96 * 64; i += 256) {
        int c = i >> 6, j = i & 63;
        Xs[c][j] = x[((b * 96) + c) * NN + n0 + j];
    }
    int oz = tid >> 6;   // 0..3
    int j  = tid & 63;
    float s2 = 0.f;

    for (int oc = 0; oc < 3; oc++) {
        __syncthreads();
        for (int i = tid; i < 32 * 96; i += 256) {
            int oo = i / 96, c = i % 96;
            Ws[oo][c] = w[(oc * 32 + oo) * 96 + c];
        }
        __syncthreads();
        float acc[8];
#pragma unroll
        for (int q = 0; q < 8; q++) acc[q] = bias[oc * 32 + oz * 8 + q];
        for (int c = 0; c < 96; c++) {
            float xc = Xs[c][j];
#pragma unroll
            for (int q = 0; q < 8; q++) acc[q] += Ws[oz * 8 + q][c] * xc;
        }
#pragma unroll
        for (int q = 0; q < 8; q++) {
            int o = oc * 32 + oz * 8 + q;
            g_h[((b * 96) + o) * NN + n0 + j] = acc[q];
            s2 += acc[q] * acc[q];
        }
    }
    S2[tid] = s2;
    __syncthreads();
    if (oz == 0) {
        float t = S2[j] + S2[64 + j] + S2[128 + j] + S2[192 + j];
        g_x2[b * NN + n0 + j] = t;
    }
}

// ---------------- K2: distance GEMM, 128x128 tiles, symmetric triangle ----------------
// grid: (325 triangle pairs, 4 batches), block 256, 8x8 per thread, BK=16 double-buffered
__global__ void __launch_bounds__(256, 2) k_dist() {
    int p = blockIdx.x;
    int b = blockIdx.y;
    // decode (bi, bj), bi <= bj, from linear triangle index
    int bj = (int)((sqrtf(8.0f * (float)p + 1.0f) - 1.0f) * 0.5f);
    while ((bj + 1) * (bj + 2) / 2 <= p) bj++;
    while (bj * (bj + 1) / 2 > p) bj--;
    int bi = p - bj * (bj + 1) / 2;

    __shared__ __align__(16) float As[2][16][128];
    __shared__ __align__(16) float Bs[2][16][128];

    int tid = threadIdx.x, tx = tid & 15, ty = tid >> 4;
    int ni0 = bi * 128, nj0 = bj * 128;
    const float* hb = g_h + (size_t)b * 96 * NN;

    // loader slots: 512 float4 per operand per stage; thread handles slots tid, tid+256
    int s0 = tid, s1 = tid + 256;
    int k0 = s0 >> 5, m0 = (s0 & 31) * 4;
    int k1 = s1 >> 5, m1 = (s1 & 31) * 4;

    float4 pa0, pa1, pb0, pb1;
    const float4 z4 = make_float4(0.f, 0.f, 0.f, 0.f);

#define LDG_TILE(kc)                                                                 \
    {                                                                                \
        int c0 = (kc) * 16 + k0, c1 = (kc) * 16 + k1;                                \
        pa0 = (ni0 + m0 < NN) ? *(const float4*)(hb + (size_t)c0 * NN + ni0 + m0) : z4; \
        pa1 = (ni0 + m1 < NN) ? *(const float4*)(hb + (size_t)c1 * NN + ni0 + m1) : z4; \
        pb0 = (nj0 + m0 < NN) ? *(const float4*)(hb + (size_t)c0 * NN + nj0 + m0) : z4; \
        pb1 = (nj0 + m1 < NN) ? *(const float4*)(hb + (size_t)c1 * NN + nj0 + m1) : z4; \
    }
#define STS_TILE(buf)                                                                \
    {                                                                                \
        *(float4*)&As[buf][k0][m0] = pa0; *(float4*)&As[buf][k1][m1] = pa1;          \
        *(float4*)&Bs[buf][k0][m0] = pb0; *(float4*)&Bs[buf][k1][m1] = pb1;          \
    }

    float acc[8][8];
#pragma unroll
    for (int i = 0; i < 8; i++)
#pragma unroll
        for (int j = 0; j < 8; j++) acc[i][j] = 0.f;

    LDG_TILE(0);
    STS_TILE(0);

    for (int kc = 0; kc < 6; kc++) {
        __syncthreads();
        if (kc < 5) LDG_TILE(kc + 1);
        int buf = kc & 1;
#pragma unroll
        for (int k = 0; k < 16; k++) {
            float4 a0 = *(const float4*)&As[buf][k][ty * 4];
            float4 a1 = *(const float4*)&As[buf][k][64 + ty * 4];
            float4 b0 = *(const float4*)&Bs[buf][k][tx * 4];
            float4 b1 = *(const float4*)&Bs[buf][k][64 + tx * 4];
            float ar[8] = {a0.x, a0.y, a0.z, a0.w, a1.x, a1.y, a1.z, a1.w};
            float br[8] = {b0.x, b0.y, b0.z, b0.w, b1.x, b1.y, b1.z, b1.w};
#pragma unroll
            for (int i = 0; i < 8; i++)
#pragma unroll
                for (int j = 0; j < 8; j++) acc[i][j] += ar[i] * br[j];
        }
        if (kc < 5) STS_TILE((kc + 1) & 1);
    }
#undef LDG_TILE
#undef STS_TILE

    // x2 vectors for rows/cols this thread owns
    float x2i[8], x2j[8];
#pragma unroll
    for (int g = 0; g < 2; g++)
#pragma unroll
        for (int q = 0; q < 4; q++) {
            int ni = ni0 + g * 64 + ty * 4 + q;
            int nj = nj0 + g * 64 + tx * 4 + q;
            x2i[g * 4 + q] = (ni < NN) ? g_x2[b * NN + ni] : 0.f;
            x2j[g * 4 + q] = (nj < NN) ? g_x2[b * NN + nj] : 0.f;
        }

    // upper write: D[ni][nj] = x2[nj] - 2*inner
#pragma unroll
    for (int rg = 0; rg < 2; rg++)
#pragma unroll
        for (int r = 0; r < 4; r++) {
            int ni = ni0 + rg * 64 + ty * 4 + r;
            if (ni < NN) {
                int ri = rg * 4 + r;
#pragma unroll
                for (int cg = 0; cg < 2; cg++) {
                    int cb = nj0 + cg * 64 + tx * 4;
                    if (cb < NN) {
                        float4 v;
                        v.x = x2j[cg * 4 + 0] - 2.f * acc[ri][cg * 4 + 0];
                        v.y = x2j[cg * 4 + 1] - 2.f * acc[ri][cg * 4 + 1];
                        v.z = x2j[cg * 4 + 2] - 2.f * acc[ri][cg * 4 + 2];
                        v.w = x2j[cg * 4 + 3] - 2.f * acc[ri][cg * 4 + 3];
                        *(float4*)&g_D[((size_t)(b * NN + ni)) * NN + cb] = v;
                    }
                }
            }
        }

    // mirror write: D[nj][ni] = x2[ni] - 2*inner
    if (bi < bj) {
#pragma unroll
        for (int cg = 0; cg < 2; cg++)
#pragma unroll
            for (int jj = 0; jj < 4; jj++) {
                int nj = nj0 + cg * 64 + tx * 4 + jj;
                if (nj < NN) {
                    int ci = cg * 4 + jj;
#pragma unroll
                    for (int rg = 0; rg < 2; rg++) {
                        int rb = ni0 + rg * 64 + ty * 4;
                        if (rb < NN) {
                            float4 v;
                            v.x = x2i[rg * 4 + 0] - 2.f * acc[rg * 4 + 0][ci];
                            v.y = x2i[rg * 4 + 1] - 2.f * acc[rg * 4 + 1][ci];
                            v.z = x2i[rg * 4 + 2] - 2.f * acc[rg * 4 + 2][ci];
                            v.w = x2i[rg * 4 + 3] - 2.f * acc[rg * 4 + 3][ci];
                            *(float4*)&g_D[((size_t)(b * NN + nj)) * NN + rb] = v;
                        }
                    }
                }
            }
    }
}

// ---------------- K3: top-9 smallest per row (warp per row, unsorted buffer) ----------------
__global__ void k_topk() {
    int warp = threadIdx.x >> 5;
    int lane = threadIdx.x & 31;
    int row = blockIdx.x * 8 + warp;  // b*NN + n
    const float4* Drow = (const float4*)(g_D + (size_t)row * NN);

    float bd[9];
    int   bix[9];
#pragma unroll
    for (int p = 0; p < 9; p++) { bd[p] = FLT_MAX; bix[p] = 0x7fffffff; }
    float wd = FLT_MAX; int wi = 0x7fffffff; int wp = 8;

    for (int s = lane; s < NN / 4; s += 32) {   // 784 float4 slots
        float4 v = Drow[s];
        int base = s * 4;
        float dv[4] = {v.x, v.y, v.z, v.w};
#pragma unroll
        for (int q = 0; q < 4; q++) {
            float d = dv[q];
            int id = base + q;
            if (d < wd || (d == wd && id < wi)) {
                bd[wp] = d; bix[wp] = id;
                // rescan for new worst (lexicographic max)
                wd = bd[0]; wi = bix[0]; wp = 0;
#pragma unroll
                for (int p2 = 1; p2 < 9; p2++)
                    if (bd[p2] > wd || (bd[p2] == wd && bix[p2] > wi)) {
                        wd = bd[p2]; wi = bix[p2]; wp = p2;
                    }
            }
        }
    }

    // 9 rounds: warp-wide lexicographic argmin, pop winner
    for (int kk = 0; kk < 9; kk++) {
        float md = bd[0]; int mi = bix[0]; int mp = 0;
#pragma unroll
        for (int p = 1; p < 9; p++)
            if (bd[p] < md || (bd[p] == md && bix[p] < mi)) { md = bd[p]; mi = bix[p]; mp = p; }
        float d = md; int ix = mi;
#pragma unroll
        for (int off = 16; off > 0; off >>= 1) {
            float od = __shfl_down_sync(0xffffffffu, d, off);
            int   oi = __shfl_down_sync(0xffffffffu, ix, off);
            if (od < d || (od == d && oi < ix)) { d = od; ix = oi; }
        }
        ix = __shfl_sync(0xffffffffu, ix, 0);
        if (mi == ix) { bd[mp] = FLT_MAX; bix[mp] = 0x7fffffff; }  // indices unique per warp
        if (lane == 0) g_idx[row * 9 + kk] = ix;
    }
}

// ---------------- K4: u/v GEMM (384x96 @ 96xN), node-major output via smem transpose ----------------
__global__ void k_uv(const float* __restrict__ gw, const float* __restrict__ gb) {
    int bn = blockIdx.x;       // n tile (0..48)
    int br = blockIdx.y;       // row tile of 384 (0..5)
    int b  = blockIdx.z;

    __shared__ __align__(16) float smbuf[6400];              // 25600 bytes
    float (*A)[52]   = (float(*)[52])smbuf;                  // [64 rows][48 k + pad]
    float (*Bsh)[64] = (float(*)[64])(smbuf + 64 * 52);      // [48 k][64 n]
    float (*C)[65]   = (float(*)[65])smbuf;                  // [64 n][64 r + pad] (reused)

    int tid = threadIdx.x, tx = tid & 15, ty = tid >> 4;
    int r0 = br * 64, n0 = bn * 64;
    bool is_u = (r0 < 192);
    const float* hb = g_h + (size_t)b * 96 * NN;
    float acc[4][4] = {};

    for (int kc = 0; kc < 2; kc++) {
        __syncthreads();
        for (int i = tid; i < 64 * 48; i += 256) {
            int rl = i / 48, cl = i % 48;
            int c = kc * 48 + cl;
            int r = r0 + rl;
            float wv;
            if (is_u) wv = gw[r * 192 + c] - gw[r * 192 + 96 + c];
            else      wv = gw[(r - 192) * 192 + 96 + c];
            A[rl][cl] = wv;
        }
        for (int i = tid; i < 48 * 64; i += 256) {
            int c = i >> 6, jj = i & 63;
            Bsh[c][jj] = hb[(kc * 48 + c) * NN + n0 + jj];
        }
        __syncthreads();
#pragma unroll
        for (int k4 = 0; k4 < 48; k4 += 4) {
            float4 a0 = *(const float4*)&A[ty * 4 + 0][k4];
            float4 a1 = *(const float4*)&A[ty * 4 + 1][k4];
            float4 a2 = *(const float4*)&A[ty * 4 + 2][k4];
            float4 a3 = *(const float4*)&A[ty * 4 + 3][k4];
            float4 b0 = *(const float4*)&Bsh[k4 + 0][tx * 4];
            float4 b1 = *(const float4*)&Bsh[k4 + 1][tx * 4];
            float4 b2 = *(const float4*)&Bsh[k4 + 2][tx * 4];
            float4 b3 = *(const float4*)&Bsh[k4 + 3][tx * 4];
            float ar[4][4] = {{a0.x,a0.y,a0.z,a0.w},{a1.x,a1.y,a1.z,a1.w},
                              {a2.x,a2.y,a2.z,a2.w},{a3.x,a3.y,a3.z,a3.w}};
            float br2[4][4] = {{b0.x,b0.y,b0.z,b0.w},{b1.x,b1.y,b1.z,b1.w},
                               {b2.x,b2.y,b2.z,b2.w},{b3.x,b3.y,b3.z,b3.w}};
#pragma unroll
            for (int ii = 0; ii < 4; ii++)
#pragma unroll
                for (int jj = 0; jj < 4; jj++)
#pragma unroll
                    for (int kk = 0; kk < 4; kk++)
                        acc[ii][jj] += ar[ii][kk] * br2[kk][jj];
        }
    }

    // transpose through smem: C[n_local][r_local], then coalesced stores
    __syncthreads();
#pragma unroll
    for (int ii = 0; ii < 4; ii++)
#pragma unroll
        for (int jj = 0; jj < 4; jj++)
            C[tx * 4 + jj][ty * 4 + ii] = acc[ii][jj];
    __syncthreads();
    for (int i = tid; i < 64 * 64; i += 256) {
        int n = i >> 6, r = i & 63;
        float val = C[n][r] + (is_u ? gb[r0 + r] : 0.f);
        g_uv[((size_t)(b * NN) + n0 + n) * 384 + r0 + r] = val;
    }
}

// ---------------- K5: gather+maxpool+relu + fc2 + channel avg/max ----------------
__global__ void k_gfc2(const float* __restrict__ fw, const float* __restrict__ fb) {
    __shared__ float Wf[32][193];
    __shared__ float gs[8][192];
    int tid = threadIdx.x;
    int warp = tid >> 5, lane = tid & 31;
    int node = blockIdx.x * 8 + warp;       // b*NN + n
    int b = node / NN, n = node % NN;
    const float* uvb = g_uv + (size_t)b * NN * 384;

    int nb[9];
#pragma unroll
    for (int k = 0; k < 9; k++) nb[k] = g_idx[node * 9 + k];

#pragma unroll
    for (int s = 0; s < 6; s++) {
        int c = lane + 32 * s;
        float u = uvb[(size_t)n * 384 + c];
        float m = -FLT_MAX;
#pragma unroll
        for (int k = 0; k < 9; k++)
            m = fmaxf(m, uvb[(size_t)nb[k] * 384 + 192 + c]);
        gs[warp][c] = fmaxf(u + m, 0.f);
    }
    __syncwarp();

    float ssum = 0.f, smax = -FLT_MAX;
    for (int ch = 0; ch < 3; ch++) {
        __syncthreads();
        for (int i = tid; i < 32 * 192; i += 256) {
            int oo = i / 192, c = i % 192;
            Wf[oo][c] = fw[(ch * 32 + oo) * 192 + c];
        }
        __syncthreads();
        int o = ch * 32 + lane;
        float a = fb[o];
        for (int c = 0; c < 192; c++) a += Wf[lane][c] * gs[warp][c];
        g_out[((b * 96) + o) * NN + n] = a;
        ssum += a;
        smax = fmaxf(smax, a);
    }
#pragma unroll
    for (int off = 16; off > 0; off >>= 1) {
        ssum += __shfl_down_sync(0xffffffffu, ssum, off);
        smax = fmaxf(smax, __shfl_down_sync(0xffffffffu, smax, off));
    }
    if (lane == 0) {
        g_avg[b * NN + n] = ssum * (1.f / 96.f);
        g_mx[b * NN + n] = smax;
    }
}

// ---------------- K6: 7x7 spatial attention + sigmoid + residual ----------------
__global__ void k_att(const float* __restrict__ sw_g, const float* __restrict__ x,
                      float* __restrict__ out) {
    __shared__ float sw[98];
    int tid = threadIdx.x;
    if (tid < 98) sw[tid] = sw_g[tid];
    __syncthreads();
    int b = blockIdx.y;
    int n = blockIdx.x * 256 + tid;
    if (n >= NN) return;
    int y = n / HH, x0 = n % HH;
    const float* avgb = g_avg + b * NN;
    const float* mxb  = g_mx + b * NN;
    float acc = 0.f;
#pragma unroll
    for (int dy = 0; dy < 7; dy++) {
        int yy = y + dy - 3;
        if ((unsigned)yy < HH) {
#pragma unroll
            for (int dx = 0; dx < 7; dx++) {
                int xx = x0 + dx - 3;
                if ((unsigned)xx < HH) {
                    int nn = yy * HH + xx;
                    acc += sw[dy * 7 + dx] * avgb[nn] + sw[49 + dy * 7 + dx] * mxb[nn];
                }
            }
        }
    }
    float att = 1.f / (1.f + expf(-acc));
    for (int o = 0; o < 96; o++) {
        size_t off = ((size_t)(b * 96 + o)) * NN + n;
        out[off] = g_out[off] * att + x[off];
    }
}

// ---------------- launch ----------------
extern "C" void kernel_launch(void* const* d_in, const int* in_sizes, int n_in,
                              void* d_out, int out_size) {
    const float* x       = (const float*)d_in[0];
    const float* fc1_w   = (const float*)d_in[1];
    const float* fc1_b   = (const float*)d_in[2];
    const float* gconv_w = (const float*)d_in[3];
    const float* gconv_b = (const float*)d_in[4];
    const float* fc2_w   = (const float*)d_in[5];
    const float* fc2_b   = (const float*)d_in[6];
    const float* sa_w    = (const float*)d_in[7];
    float* out = (float*)d_out;

    k_fc1 <<<dim3(49, 4), 256>>>(x, fc1_w, fc1_b);
    k_dist<<<dim3(325, 4), 256>>>();
    k_topk<<<1568, 256>>>();
    k_uv  <<<dim3(49, 6, 4), 256>>>(gconv_w, gconv_b);
    k_gfc2<<<1568, 256>>>(fc2_w, fc2_b);
    k_att <<<dim3(13, 4), 256>>>(sa_w, x, out);
}